// round 2
// baseline (speedup 1.0000x reference)
#include <cuda_runtime.h>
#include <math.h>

// GRU recurrence, persistent kernel.
// B=256, T=2048, H=150 (3H=450 gate rows), I=1, O=1.
// 128 CTAs x 480 threads; each CTA owns batches (2*cta, 2*cta+1).
// Thread t owns gate-row j=t (rows padded to 480; rows>=450 are zero).
// W_hh row split: k in [0,80) in registers, k in [80,152) (padded) in SMEM.

#define NTHREADS 480
#define NROWS    480
#define HID      150
#define G3       450
#define TLEN     2048
#define KREG     80
#define MSM      18            // float4 groups in SMEM per row: k = 80..151 (k>=150 zero)
#define HQ_N     76            // float4 h entries (k pairs 0..151), entry 75 stays zero

// SMEM float layout:
//   sW   : MSM*NROWS float4  = 34560 floats
//   hq   : HQ_N float4       =   304 floats   (hq[kk] = {h0[2kk],h1[2kk],h0[2kk+1],h1[2kk+1]})
//   gh2  : NROWS float2      =   960 floats
//   px   : 160 floats
//   py   : 160 floats
#define SMEM_FLOATS (MSM*NROWS*4 + HQ_N*4 + NROWS*2 + 160 + 160)

__device__ __forceinline__ float sigf(float v) {
    return 1.0f / (1.0f + __expf(-v));
}

extern "C" __global__ void __launch_bounds__(NTHREADS, 1)
gru_persistent(const float* __restrict__ x,     // [B][T]
               const float* __restrict__ Wih,   // [450][1]
               const float* __restrict__ Whh,   // [450][150]
               const float* __restrict__ bih,   // [450]
               const float* __restrict__ bhh,   // [450]
               const float* __restrict__ Wlin,  // [1][150]
               const float* __restrict__ blin,  // [1]
               float* __restrict__ out)         // [B][T]
{
    extern __shared__ float smem[];
    float4* sW  = (float4*)smem;                            // [MSM][NROWS]
    float4* hq  = (float4*)(smem + MSM*NROWS*4);            // [HQ_N]
    float*  bse = smem + MSM*NROWS*4 + HQ_N*4;
    float2* gh2 = (float2*)bse;                             // [NROWS]
    float*  px  = bse + NROWS*2;                            // [160]
    float*  py  = px + 160;                                 // [160]
    float2* hp  = (float2*)hq;                              // hp[k] = (h0[k], h1[k])

    const int tid = threadIdx.x;
    const int b0  = blockIdx.x * 2;
    const int b1  = b0 + 1;

    // ---------------- init: distribute W ----------------
    float wreg[KREG];
    float wih_j = 0.0f, bias_j = 0.0f;
    if (tid < G3) {
        // rows < 300 (r,z): bias = b_ih + b_hh, input weight active.
        // rows >= 300 (n):  matvec carries b_hh only (lives inside r*(.)); i_n handled at gate stage.
        wih_j  = (tid < 2 * HID) ? Wih[tid] : 0.0f;
        bias_j = (tid < 2 * HID) ? (bih[tid] + bhh[tid]) : bhh[tid];
        const float* wr = Whh + tid * HID;
        #pragma unroll
        for (int k = 0; k < KREG; k++) wreg[k] = wr[k];
        #pragma unroll
        for (int m = 0; m < MSM; m++) {
            const int k = KREG + 4 * m;
            float4 v;
            v.x = (k + 0 < HID) ? wr[k + 0] : 0.0f;
            v.y = (k + 1 < HID) ? wr[k + 1] : 0.0f;
            v.z = (k + 2 < HID) ? wr[k + 2] : 0.0f;
            v.w = (k + 3 < HID) ? wr[k + 3] : 0.0f;
            sW[m * NROWS + tid] = v;
        }
    } else {
        #pragma unroll
        for (int k = 0; k < KREG; k++) wreg[k] = 0.0f;
        #pragma unroll
        for (int m = 0; m < MSM; m++) sW[m * NROWS + tid] = make_float4(0.f, 0.f, 0.f, 0.f);
    }

    // gate-stage extras for hidden unit u = tid (< 150)
    float win = 0.0f, bin = 0.0f, wlin = 0.0f;
    if (tid < HID) {
        win  = Wih[2 * HID + tid];
        bin  = bih[2 * HID + tid];
        wlin = Wlin[tid];
    }
    const float bl = __ldg(blin);

    if (tid < HQ_N) hq[tid] = make_float4(0.f, 0.f, 0.f, 0.f);   // h0 = 0 (+ zero pad entry 75)
    __syncthreads();

    const float* xr0 = x + (size_t)b0 * TLEN;
    const float* xr1 = x + (size_t)b1 * TLEN;
    float* or0 = out + (size_t)b0 * TLEN;
    float* or1 = out + (size_t)b1 * TLEN;

    // ---------------- time loop ----------------
    for (int t = 0; t < TLEN; t++) {
        const float x0 = __ldg(xr0 + t);
        const float x1 = __ldg(xr1 + t);

        float acc0 = fmaf(x0, wih_j, bias_j);
        float acc1 = fmaf(x1, wih_j, bias_j);

        // k = 0..79 : W in registers, h via broadcast LDS.128
        #pragma unroll
        for (int g = 0; g < KREG / 4; g++) {
            const float4 q0 = hq[2 * g];
            const float4 q1 = hq[2 * g + 1];
            acc0 = fmaf(wreg[4 * g + 0], q0.x, acc0);
            acc1 = fmaf(wreg[4 * g + 0], q0.y, acc1);
            acc0 = fmaf(wreg[4 * g + 1], q0.z, acc0);
            acc1 = fmaf(wreg[4 * g + 1], q0.w, acc1);
            acc0 = fmaf(wreg[4 * g + 2], q1.x, acc0);
            acc1 = fmaf(wreg[4 * g + 2], q1.y, acc1);
            acc0 = fmaf(wreg[4 * g + 3], q1.z, acc0);
            acc1 = fmaf(wreg[4 * g + 3], q1.w, acc1);
        }
        // k = 80..151 : W in SMEM (lane-consecutive float4, conflict-free)
        #pragma unroll
        for (int m = 0; m < MSM; m++) {
            const float4 w4 = sW[m * NROWS + tid];
            const int   kk  = KREG / 2 + 2 * m;
            const float4 q0 = hq[kk];
            const float4 q1 = hq[kk + 1];
            acc0 = fmaf(w4.x, q0.x, acc0);
            acc1 = fmaf(w4.x, q0.y, acc1);
            acc0 = fmaf(w4.y, q0.z, acc0);
            acc1 = fmaf(w4.y, q0.w, acc1);
            acc0 = fmaf(w4.z, q1.x, acc0);
            acc1 = fmaf(w4.z, q1.y, acc1);
            acc0 = fmaf(w4.w, q1.z, acc0);
            acc1 = fmaf(w4.w, q1.w, acc1);
        }

        gh2[tid] = make_float2(acc0, acc1);
        __syncthreads();

        // gate stage: thread u < 150 updates hidden unit u for both batches
        if (tid < HID) {
            const float2 gr = gh2[tid];
            const float2 gz = gh2[tid + HID];
            const float2 gn = gh2[tid + 2 * HID];
            const float2 hold = hp[tid];

            const float in0 = fmaf(x0, win, bin);
            const float in1 = fmaf(x1, win, bin);

            const float r0 = sigf(gr.x);
            const float r1 = sigf(gr.y);
            const float z0 = sigf(gz.x);
            const float z1 = sigf(gz.y);
            const float n0 = tanhf(fmaf(r0, gn.x, in0));
            const float n1 = tanhf(fmaf(r1, gn.y, in1));

            const float h0n = fmaxf(0.0f, fmaf(z0, hold.x - n0, n0));
            const float h1n = fmaxf(0.0f, fmaf(z1, hold.y - n1, n1));

            hp[tid] = make_float2(h0n, h1n);
            px[tid] = h0n * wlin;
            py[tid] = h1n * wlin;
        }
        __syncthreads();

        // y head: warp 0 -> b0, warp 1 -> b1 (overlaps other warps' next matvec)
        const int w    = tid >> 5;
        const int lane = tid & 31;
        if (w < 2) {
            const float* p = w ? py : px;
            float s = p[lane] + p[lane + 32] + p[lane + 64] + p[lane + 96]
                    + ((lane + 128 < HID) ? p[lane + 128] : 0.0f);
            s += __shfl_xor_sync(0xffffffffu, s, 16);
            s += __shfl_xor_sync(0xffffffffu, s, 8);
            s += __shfl_xor_sync(0xffffffffu, s, 4);
            s += __shfl_xor_sync(0xffffffffu, s, 2);
            s += __shfl_xor_sync(0xffffffffu, s, 1);
            if (lane == 0) {
                (w ? or1 : or0)[t] = s + bl;
            }
        }
    }
}

extern "C" void kernel_launch(void* const* d_in, const int* in_sizes, int n_in,
                              void* d_out, int out_size) {
    const float* x    = (const float*)d_in[0];
    const float* Wih  = (const float*)d_in[1];
    const float* Whh  = (const float*)d_in[2];
    const float* bih  = (const float*)d_in[3];
    const float* bhh  = (const float*)d_in[4];
    const float* Wlin = (const float*)d_in[5];
    const float* blin = (const float*)d_in[6];
    float* out = (float*)d_out;

    const size_t smem_bytes = SMEM_FLOATS * sizeof(float);   // 144,576 B
    cudaFuncSetAttribute(gru_persistent,
                         cudaFuncAttributeMaxDynamicSharedMemorySize,
                         (int)smem_bytes);

    gru_persistent<<<128, NTHREADS, smem_bytes>>>(x, Wih, Whh, bih, bhh, Wlin, blin, out);
}

// round 4
// speedup vs baseline: 1.2700x; 1.2700x over previous
#include <cuda_runtime.h>
#include <math.h>

// GRU recurrence, persistent kernel, round 2.
// B=256, T=2048, H=150 (3H=450 gate rows), I=O=1.
// 128 CTAs x 256 threads; CTA owns batches (2*cta, 2*cta+1).
// Thread t owns gate-rows t and t+256 (rows padded to 512; rows>=450 zero).
// W_hh per row: k in [0,88) in registers as packed f32x2 pairs; k in [88,152) in SMEM.
// Matvec uses fma.rn.f32x2 (2 MACs/instr). h stored per-batch contiguous so an
// LDS.128 (ulonglong2) yields two f32x2 operands directly.

#define NTHREADS 256
#define NROWS    512
#define HID      150
#define G3       450
#define TLEN     2048
#define KPAD     152
#define KREG     88            // floats of W per row in registers (44 u64 pairs)
#define NGREG    22            // 4-float groups from registers
#define NGSM     16            // 4-float groups from SMEM (k = 88..151)
#define NGTOT    38            // KPAD/4

// SMEM layout (floats):
#define OFF_SW   0                         // ulonglong2 [NGSM][NROWS] = 32768 floats
#define OFF_SX0  (NGSM*NROWS*4)            // 2048
#define OFF_SX1  (OFF_SX0 + TLEN)          // 2048
#define OFF_H0   (OFF_SX1 + TLEN)          // 160
#define OFF_H1   (OFF_H0 + 160)            // 160
#define OFF_GH0  (OFF_H1 + 160)            // 512
#define OFF_GH1  (OFF_GH0 + NROWS)         // 512
#define OFF_PX   (OFF_GH1 + NROWS)         // 160
#define OFF_PY   (OFF_PX + 160)            // 160
#define SMEM_FLOATS (OFF_PY + 160)

typedef unsigned long long u64;

#define FFMA2(d, a, b) asm("fma.rn.f32x2 %0, %1, %2, %0;" : "+l"(d) : "l"(a), "l"(b))

__device__ __forceinline__ u64 pack2(float a, float b) {
    u64 r; asm("mov.b64 %0, {%1, %2};" : "=l"(r) : "f"(a), "f"(b)); return r;
}
__device__ __forceinline__ float rsum2(u64 v) {
    float lo, hi; asm("mov.b64 {%0, %1}, %2;" : "=f"(lo), "=f"(hi) : "l"(v));
    return lo + hi;
}
__device__ __forceinline__ float sigf(float v) {
    return 1.0f / (1.0f + __expf(-v));
}
__device__ __forceinline__ float tanhfast(float v) {
    float e = __expf(-2.0f * v);
    return __fdividef(1.0f - e, 1.0f + e);
}

extern "C" __global__ void __launch_bounds__(NTHREADS, 1)
gru_persistent(const float* __restrict__ x,     // [B][T]
               const float* __restrict__ Wih,   // [450][1]
               const float* __restrict__ Whh,   // [450][150]
               const float* __restrict__ bih,   // [450]
               const float* __restrict__ bhh,   // [450]
               const float* __restrict__ Wlin,  // [1][150]
               const float* __restrict__ blin,  // [1]
               float* __restrict__ out)         // [B][T]
{
    extern __shared__ float smem[];
    ulonglong2* sWv = (ulonglong2*)(smem + OFF_SW);   // [NGSM][NROWS]
    float* sx0 = smem + OFF_SX0;
    float* sx1 = smem + OFF_SX1;
    float* h0s = smem + OFF_H0;
    float* h1s = smem + OFF_H1;
    float* gh0 = smem + OFF_GH0;
    float* gh1 = smem + OFF_GH1;
    float* px  = smem + OFF_PX;
    float* py  = smem + OFF_PY;
    const ulonglong2* h0v = (const ulonglong2*)h0s;   // [NGTOT]
    const ulonglong2* h1v = (const ulonglong2*)h1s;

    const int tid = threadIdx.x;
    const int b0  = blockIdx.x * 2;
    const int r0  = tid;
    const int r1  = tid + NTHREADS;

    // ---------------- init ----------------
    // W register part: packed pairs for both rows.
    u64 w0[KREG / 2], w1[KREG / 2];
    {
        const float* wr0 = Whh + r0 * HID;
        const float* wr1 = Whh + r1 * HID;
        #pragma unroll
        for (int p = 0; p < KREG / 2; p++) {
            int k = 2 * p;
            float a0 = (r0 < G3) ? wr0[k]     : 0.0f;
            float a1 = (r0 < G3) ? wr0[k + 1] : 0.0f;
            float c0 = (r1 < G3) ? wr1[k]     : 0.0f;
            float c1 = (r1 < G3) ? wr1[k + 1] : 0.0f;
            w0[p] = pack2(a0, a1);
            w1[p] = pack2(c0, c1);
        }
        // W SMEM part
        #pragma unroll
        for (int gs = 0; gs < NGSM; gs++) {
            int k = KREG + 4 * gs;
            float4 v0, v1;
            v0.x = (r0 < G3 && k + 0 < HID) ? wr0[k + 0] : 0.0f;
            v0.y = (r0 < G3 && k + 1 < HID) ? wr0[k + 1] : 0.0f;
            v0.z = (r0 < G3 && k + 2 < HID) ? wr0[k + 2] : 0.0f;
            v0.w = (r0 < G3 && k + 3 < HID) ? wr0[k + 3] : 0.0f;
            v1.x = (r1 < G3 && k + 0 < HID) ? wr1[k + 0] : 0.0f;
            v1.y = (r1 < G3 && k + 1 < HID) ? wr1[k + 1] : 0.0f;
            v1.z = (r1 < G3 && k + 2 < HID) ? wr1[k + 2] : 0.0f;
            v1.w = (r1 < G3 && k + 3 < HID) ? wr1[k + 3] : 0.0f;
            ((float4*)sWv)[gs * NROWS + r0] = v0;
            ((float4*)sWv)[gs * NROWS + r1] = v1;
        }
    }

    // Per-row bias / input weight (rows >= 300 carry b_hh only in the matvec;
    // i_n = x*W_ih + b_ih enters at the gate stage inside r*(.)-free term).
    float wih0 = 0.0f, bias0 = 0.0f, wih1 = 0.0f, bias1 = 0.0f;
    if (r0 < G3) {
        wih0  = (r0 < 2 * HID) ? Wih[r0] : 0.0f;
        bias0 = (r0 < 2 * HID) ? (bih[r0] + bhh[r0]) : bhh[r0];
    }
    if (r1 < G3) {
        wih1  = (r1 < 2 * HID) ? Wih[r1] : 0.0f;
        bias1 = (r1 < 2 * HID) ? (bih[r1] + bhh[r1]) : bhh[r1];
    }

    float win = 0.0f, bin = 0.0f, wlin = 0.0f;
    if (tid < HID) {
        win  = Wih[2 * HID + tid];
        bin  = bih[2 * HID + tid];
        wlin = Wlin[tid];
    }
    const float bl = __ldg(blin);

    // Stage x rows into SMEM (coalesced)
    const float* xr0 = x + (size_t)b0 * TLEN;
    const float* xr1 = x + (size_t)(b0 + 1) * TLEN;
    for (int i = tid; i < TLEN; i += NTHREADS) {
        sx0[i] = xr0[i];
        sx1[i] = xr1[i];
    }
    for (int i = tid; i < 160; i += NTHREADS) { h0s[i] = 0.0f; h1s[i] = 0.0f; }
    __syncthreads();

    float* or0 = out + (size_t)b0 * TLEN;
    float* or1 = out + (size_t)(b0 + 1) * TLEN;

    // ---------------- time loop ----------------
    for (int t = 0; t < TLEN; t++) {
        const float x0 = sx0[t];
        const float x1 = sx1[t];

        // 8 accumulators: [row][batch][x/y half-group]
        u64 a00x = 0, a00y = 0, a01x = 0, a01y = 0;
        u64 a10x = 0, a10y = 0, a11x = 0, a11y = 0;

        // k = 0..87 : W in registers
        #pragma unroll
        for (int g = 0; g < NGREG; g++) {
            const ulonglong2 q0 = h0v[g];
            const ulonglong2 q1 = h1v[g];
            const u64 wa = w0[2 * g], wb = w0[2 * g + 1];
            const u64 wc = w1[2 * g], wd = w1[2 * g + 1];
            FFMA2(a00x, wa, q0.x); FFMA2(a01x, wa, q1.x);
            FFMA2(a10x, wc, q0.x); FFMA2(a11x, wc, q1.x);
            FFMA2(a00y, wb, q0.y); FFMA2(a01y, wb, q1.y);
            FFMA2(a10y, wd, q0.y); FFMA2(a11y, wd, q1.y);
        }
        // k = 88..151 : W in SMEM (lane-consecutive ulonglong2, conflict-free)
        #pragma unroll
        for (int gs = 0; gs < NGSM; gs++) {
            const ulonglong2 wv0 = sWv[gs * NROWS + r0];
            const ulonglong2 wv1 = sWv[gs * NROWS + r1];
            const ulonglong2 q0  = h0v[NGREG + gs];
            const ulonglong2 q1  = h1v[NGREG + gs];
            FFMA2(a00x, wv0.x, q0.x); FFMA2(a01x, wv0.x, q1.x);
            FFMA2(a10x, wv1.x, q0.x); FFMA2(a11x, wv1.x, q1.x);
            FFMA2(a00y, wv0.y, q0.y); FFMA2(a01y, wv0.y, q1.y);
            FFMA2(a10y, wv1.y, q0.y); FFMA2(a11y, wv1.y, q1.y);
        }

        gh0[r0] = rsum2(a00x) + rsum2(a00y) + fmaf(x0, wih0, bias0);
        gh1[r0] = rsum2(a01x) + rsum2(a01y) + fmaf(x1, wih0, bias0);
        gh0[r1] = rsum2(a10x) + rsum2(a10y) + fmaf(x0, wih1, bias1);
        gh1[r1] = rsum2(a11x) + rsum2(a11y) + fmaf(x1, wih1, bias1);
        __syncthreads();

        // gate stage: thread u < 150 updates hidden unit u for both batches
        if (tid < HID) {
            const float grA = gh0[tid];
            const float gzA = gh0[tid + HID];
            const float gnA = gh0[tid + 2 * HID];
            const float grB = gh1[tid];
            const float gzB = gh1[tid + HID];
            const float gnB = gh1[tid + 2 * HID];
            const float hA  = h0s[tid];
            const float hB  = h1s[tid];

            const float inA = fmaf(x0, win, bin);
            const float inB = fmaf(x1, win, bin);

            const float rA = sigf(grA);
            const float rB = sigf(grB);
            const float zA = sigf(gzA);
            const float zB = sigf(gzB);
            const float nA = tanhfast(fmaf(rA, gnA, inA));
            const float nB = tanhfast(fmaf(rB, gnB, inB));

            const float hAn = fmaxf(0.0f, fmaf(zA, hA - nA, nA));
            const float hBn = fmaxf(0.0f, fmaf(zB, hB - nB, nB));

            h0s[tid] = hAn;
            h1s[tid] = hBn;
            px[tid] = hAn * wlin;
            py[tid] = hBn * wlin;
        }
        __syncthreads();

        // y head: warp 0 -> batch 0, warp 1 -> batch 1 (overlaps next matvec)
        const int w    = tid >> 5;
        const int lane = tid & 31;
        if (w < 2) {
            const float* p = w ? py : px;
            float s = p[lane] + p[lane + 32] + p[lane + 64] + p[lane + 96]
                    + ((lane + 128 < HID) ? p[lane + 128] : 0.0f);
            s += __shfl_xor_sync(0xffffffffu, s, 16);
            s += __shfl_xor_sync(0xffffffffu, s, 8);
            s += __shfl_xor_sync(0xffffffffu, s, 4);
            s += __shfl_xor_sync(0xffffffffu, s, 2);
            s += __shfl_xor_sync(0xffffffffu, s, 1);
            if (lane == 0) {
                (w ? or1 : or0)[t] = s + bl;
            }
        }
    }
}

extern "C" void kernel_launch(void* const* d_in, const int* in_sizes, int n_in,
                              void* d_out, int out_size) {
    const float* x    = (const float*)d_in[0];
    const float* Wih  = (const float*)d_in[1];
    const float* Whh  = (const float*)d_in[2];
    const float* bih  = (const float*)d_in[3];
    const float* bhh  = (const float*)d_in[4];
    const float* Wlin = (const float*)d_in[5];
    const float* blin = (const float*)d_in[6];
    float* out = (float*)d_out;

    const size_t smem_bytes = SMEM_FLOATS * sizeof(float);   // ~154 KB
    cudaFuncSetAttribute(gru_persistent,
                         cudaFuncAttributeMaxDynamicSharedMemorySize,
                         (int)smem_bytes);

    gru_persistent<<<128, NTHREADS, smem_bytes>>>(x, Wih, Whh, bih, bhh, Wlin, blin, out);
}